// round 16
// baseline (speedup 1.0000x reference)
#include <cuda_runtime.h>
#include <cstdint>
#include <cstddef>

#define B_  8
#define C_  64
#define N_  4096
#define N4_ 1024
#define SPLIT1 4
#define BN4 (B_*N4_)
#define PR 36
#define LOG2E 1.4426950408889634f

typedef unsigned long long u64;
typedef unsigned int u32;

// bf16 operands as bf16x2 words; per row 32 words over the 64-elt contraction
// dim, word w stored at perm p(w) = (w&3)*8 + (w>>2).
__device__ u32 g_K [B_*N_*32];          // (b,key)[32]     stage1 keys
__device__ u32 g_V [B_*C_*(N_/64)*32];  // (b,c,ktile)[32] stage1 values
__device__ u32 g_Q [B_*N_*32];          // (b,q)[32]       stage2 queries (pre-scaled by log2e)
__device__ u32 g_qp[B_*N4_*32];         // (b,j)[32]       stage1 pooled queries (pre-scaled)
__device__ u32 g_kp[B_*N4_*32];         // (b,j)[32]       stage2 keys
__device__ u32 g_vp[B_*C_*(N4_/64)*32]; // (b,c,ktile)[32] stage2 values
__device__ float g_po[SPLIT1*BN4*C_];   // split-K partials (unnormalized)
__device__ float g_m2[SPLIT1*BN4];
__device__ float g_l2[SPLIT1*BN4];

__device__ __forceinline__ u32 bf2(float lo, float hi) {
    u32 r; asm("cvt.rn.bf16x2.f32 %0, %1, %2;" : "=r"(r) : "f"(hi), "f"(lo)); return r;
}
__device__ __forceinline__ float ex2(float x) {
    float r; asm("ex2.approx.f32 %0, %1;" : "=f"(r) : "f"(x)); return r;
}
__device__ __forceinline__ int permw(int w) { return (w & 3) * 8 + (w >> 2); }

__device__ __forceinline__ void cpa16(u32* dst, const u32* src) {
    u32 d = (u32)__cvta_generic_to_shared(dst);
    asm volatile("cp.async.ca.shared.global [%0], [%1], 16;" :: "r"(d), "l"(src));
}
#define CP_COMMIT() asm volatile("cp.async.commit_group;" ::: "memory")
#define CP_WAIT0()  asm volatile("cp.async.wait_group 0;" ::: "memory")

__device__ __forceinline__ void mma_bf16(float c[4], u32 a0, u32 a1, u32 a2, u32 a3,
                                         u32 b0, u32 b1) {
    asm volatile(
        "mma.sync.aligned.m16n8k16.row.col.f32.bf16.bf16.f32 "
        "{%0,%1,%2,%3},{%4,%5,%6,%7},{%8,%9},{%0,%1,%2,%3};"
        : "+f"(c[0]), "+f"(c[1]), "+f"(c[2]), "+f"(c[3])
        : "r"(a0), "r"(a1), "r"(a2), "r"(a3), "r"(b0), "r"(b1));
}

// ================= bf16-MMA projection core (unchanged R15) ================

__device__ __forceinline__ void stage_W(const float* __restrict__ w,
                                        const float* __restrict__ bias,
                                        u32* sW, float* sb, int tid, float scale)
{
    for (int i = tid; i < 1024; i += 256) {
        int o = i >> 4, t = i & 15;
        float4 v = *(const float4*)(w + o * 64 + 4 * t);
        sW[o * PR + permw(2 * t)]     = bf2(v.x * scale, v.y * scale);
        sW[o * PR + permw(2 * t + 1)] = bf2(v.z * scale, v.w * scale);
    }
    if (tid < 64) sb[tid] = bias[tid] * scale;
}

__device__ __forceinline__ void proj_mma(const u32* sX, const u32* sW,
                                         float sc[8][4], int r0, int grp, int qd)
{
    u32 a0[8], a1[8];
    #pragma unroll
    for (int u = 0; u < 2; u++) {
        uint4 x0 = *(const uint4*)(sX + r0 * PR + 8 * qd + 4 * u);
        uint4 x1 = *(const uint4*)(sX + (r0 + 8) * PR + 8 * qd + 4 * u);
        a0[4*u] = x0.x; a0[4*u+1] = x0.y; a0[4*u+2] = x0.z; a0[4*u+3] = x0.w;
        a1[4*u] = x1.x; a1[4*u+1] = x1.y; a1[4*u+2] = x1.z; a1[4*u+3] = x1.w;
    }
    #pragma unroll
    for (int nt = 0; nt < 8; nt++) {
        sc[nt][0] = 0.f; sc[nt][1] = 0.f; sc[nt][2] = 0.f; sc[nt][3] = 0.f;
        const u32* bp = sW + (8 * nt + grp) * PR + 8 * qd;
        uint4 B0 = *(const uint4*)bp;
        uint4 B1 = *(const uint4*)(bp + 4);
        mma_bf16(sc[nt], a0[0], a1[0], a0[1], a1[1], B0.x, B0.y);
        mma_bf16(sc[nt], a0[2], a1[2], a0[3], a1[3], B0.z, B0.w);
        mma_bf16(sc[nt], a0[4], a1[4], a0[5], a1[5], B1.x, B1.y);
        mma_bf16(sc[nt], a0[6], a1[6], a0[7], a1[7], B1.z, B1.w);
    }
}

__device__ __forceinline__ void store_nmaj(u32* __restrict__ dst,
                                           const float sc[8][4], const float* sb,
                                           int r0, int qd)
{
    u32 w0[8], w1[8];
    #pragma unroll
    for (int nt = 0; nt < 8; nt++) {
        float2 bb = *(const float2*)(sb + 8 * nt + 2 * qd);
        w0[nt] = bf2(sc[nt][0] + bb.x, sc[nt][1] + bb.y);
        w1[nt] = bf2(sc[nt][2] + bb.x, sc[nt][3] + bb.y);
    }
    *(uint4*)(dst + (size_t)r0 * 32 + 8 * qd)     = make_uint4(w0[0], w0[1], w0[2], w0[3]);
    *(uint4*)(dst + (size_t)r0 * 32 + 8 * qd + 4) = make_uint4(w0[4], w0[5], w0[6], w0[7]);
    *(uint4*)(dst + (size_t)(r0 + 8) * 32 + 8 * qd)     = make_uint4(w1[0], w1[1], w1[2], w1[3]);
    *(uint4*)(dst + (size_t)(r0 + 8) * 32 + 8 * qd + 4) = make_uint4(w1[4], w1[5], w1[6], w1[7]);
}

__device__ __forceinline__ void store_cmaj128(u32* __restrict__ out, int NT, int ktbase,
                                              float* st, const float sc[8][4],
                                              const float* sb, int r0, int qd, int tid)
{
    __syncthreads();
    #pragma unroll
    for (int nt = 0; nt < 8; nt++) {
        float2 bb = *(const float2*)(sb + 8 * nt + 2 * qd);
        st[r0 * 67 + 8 * nt + 2 * qd]     = sc[nt][0] + bb.x;
        st[r0 * 67 + 8 * nt + 2 * qd + 1] = sc[nt][1] + bb.y;
        st[(r0 + 8) * 67 + 8 * nt + 2 * qd]     = sc[nt][2] + bb.x;
        st[(r0 + 8) * 67 + 8 * nt + 2 * qd + 1] = sc[nt][3] + bb.y;
    }
    __syncthreads();
    for (int i = tid; i < 4096; i += 256) {
        int w = i & 31, tile = (i >> 5) & 1, cout = i >> 6;
        float v0 = st[(tile * 64 + 2 * w) * 67 + cout];
        float v1 = st[(tile * 64 + 2 * w + 1) * 67 + cout];
        out[((size_t)cout * NT + ktbase + tile) * 32 + permw(w)] = bf2(v0, v1);
    }
}

#define PROJX_SMEM ((128*67 + 64) * 4)
__global__ __launch_bounds__(256)
void projX_kernel(const float* __restrict__ x,
                  const float* __restrict__ wK, const float* __restrict__ bK,
                  const float* __restrict__ wV, const float* __restrict__ bV,
                  const float* __restrict__ wQ, const float* __restrict__ bQ,
                  const float* __restrict__ wq, const float* __restrict__ bq)
{
    int which = blockIdx.y;
    if (which == 3 && blockIdx.x >= B_*N4_/128) return;

    extern __shared__ u32 sm[];
    u32* sX = sm;
    u32* sW = sm + 128 * PR;
    float* st = (float*)sm;
    float* sb = (float*)(sm + 128 * 67);
    int tid = threadIdx.x;
    const float* w  = which == 0 ? wK : (which == 1 ? wV : (which == 2 ? wQ : wq));
    const float* bs = which == 0 ? bK : (which == 1 ? bV : (which == 2 ? bQ : bq));
    stage_W(w, bs, sW, sb, tid, which >= 2 ? LOG2E : 1.0f);

    if (which != 3) {
        int gpos0 = blockIdx.x * 128;
        int b = gpos0 >> 12, n0 = gpos0 & (N_ - 1);
        const float* xb = x + (size_t)b * C_ * N_ + n0;
        #pragma unroll
        for (int it = 0; it < 2; it++) {
            int idx = it * 256 + tid;
            int pos = idx & 127, a = idx >> 7;
            u32 wb[8];
            #pragma unroll
            for (int j = 0; j < 8; j++) {
                int ch = 8 * j + 2 * a;
                wb[j] = bf2(xb[(size_t)ch * N_ + pos], xb[(size_t)(ch + 1) * N_ + pos]);
            }
            *(uint4*)(sX + pos * PR + 8 * a)     = make_uint4(wb[0], wb[1], wb[2], wb[3]);
            *(uint4*)(sX + pos * PR + 8 * a + 4) = make_uint4(wb[4], wb[5], wb[6], wb[7]);
        }
        __syncthreads();

        int wid = tid >> 5, lane = tid & 31, grp = lane >> 2, qd = lane & 3;
        int r0 = wid * 16 + grp;
        float sc[8][4];
        proj_mma(sX, sW, sc, r0, grp, qd);
        if (which == 0)      store_nmaj(g_K + (size_t)gpos0 * 32, sc, sb, r0, qd);
        else if (which == 2) store_nmaj(g_Q + (size_t)gpos0 * 32, sc, sb, r0, qd);
        else store_cmaj128(g_V + (size_t)b * 64 * 64 * 32, 64, n0 >> 6, st, sc, sb, r0, qd, tid);
    } else {
        int gpos0 = blockIdx.x * 128;
        int b = gpos0 >> 10, j0 = gpos0 & (N4_ - 1);
        const float* xb = x + (size_t)b * C_ * N_;
        #pragma unroll
        for (int it = 0; it < 2; it++) {
            int idx = it * 256 + tid;
            int pos = idx & 127, a = idx >> 7;
            int jj = j0 + pos;
            size_t base = (size_t)(jj >> 5) * 128 + (jj & 31) * 2;
            u32 wb[8];
            #pragma unroll
            for (int j = 0; j < 8; j++) {
                int ch = 8 * j + 2 * a;
                const float* p0 = xb + (size_t)ch * N_ + base;
                const float* p1 = xb + (size_t)(ch + 1) * N_ + base;
                float v0 = 0.25f * (p0[0] + p0[1] + p0[64] + p0[65]);
                float v1 = 0.25f * (p1[0] + p1[1] + p1[64] + p1[65]);
                wb[j] = bf2(v0, v1);
            }
            *(uint4*)(sX + pos * PR + 8 * a)     = make_uint4(wb[0], wb[1], wb[2], wb[3]);
            *(uint4*)(sX + pos * PR + 8 * a + 4) = make_uint4(wb[4], wb[5], wb[6], wb[7]);
        }
        __syncthreads();

        int wid = tid >> 5, lane = tid & 31, grp = lane >> 2, qd = lane & 3;
        int r0 = wid * 16 + grp;
        float sc[8][4];
        proj_mma(sX, sW, sc, r0, grp, qd);
        store_nmaj(g_qp + (size_t)gpos0 * 32, sc, sb, r0, qd);
    }
}

#define PC_SX   0
#define PC_SWK  (64*PR)
#define PC_SWV  (PC_SWK + 64*PR)
#define PC_ST   (PC_SWV + 64*PR)
#define PC_SB   (PC_ST + 64*67)
#define PC_SWT  (PC_SB + 128)
#define PROJC_SMEM ((PC_SWT + 256) * 4)
__global__ __launch_bounds__(256)
void projC_kernel(const float* __restrict__ wk, const float* __restrict__ bk,
                  const float* __restrict__ wv, const float* __restrict__ bv)
{
    extern __shared__ u32 sm[];
    u32* sX  = sm + PC_SX;
    u32* sWk = sm + PC_SWK;
    u32* sWv = sm + PC_SWV;
    float* st  = (float*)(sm + PC_ST);
    float* sb  = (float*)(sm + PC_SB);
    float* swt = (float*)(sm + PC_SWT);
    int tid = threadIdx.x;
    stage_W(wk, bk, sWk, sb, tid, 1.0f);
    stage_W(wv, bv, sWv, sb + 64, tid, 1.0f);

    int gpos0 = blockIdx.x * 64;
    int b = gpos0 >> 10, j0 = gpos0 & (N4_ - 1);

    if (tid < 64) {
        int grow = gpos0 + tid;
        float mv[SPLIT1], lv[SPLIT1], M = -1e30f;
        #pragma unroll
        for (int p = 0; p < SPLIT1; p++) {
            mv[p] = g_m2[p * BN4 + grow];
            lv[p] = g_l2[p * BN4 + grow];
            M = fmaxf(M, mv[p]);
        }
        float wv_[SPLIT1], ls = 0.f;
        #pragma unroll
        for (int p = 0; p < SPLIT1; p++) { wv_[p] = ex2(mv[p] - M); ls += lv[p] * wv_[p]; }
        float inv = 1.f / ls;
        #pragma unroll
        for (int p = 0; p < SPLIT1; p++) swt[tid * 4 + p] = wv_[p] * inv;
    }
    __syncthreads();

    for (int i = tid; i < 1024; i += 256) {
        int c4 = i & 15, pos = i >> 4;
        const float* wp = swt + pos * 4;
        float4 acc = make_float4(0.f, 0.f, 0.f, 0.f);
        #pragma unroll
        for (int p = 0; p < SPLIT1; p++) {
            float4 a = *(const float4*)(g_po + ((size_t)p * BN4 + gpos0 + pos) * 64 + 4 * c4);
            float wf = wp[p];
            acc.x += wf * a.x; acc.y += wf * a.y; acc.z += wf * a.z; acc.w += wf * a.w;
        }
        sX[pos * PR + permw(2 * c4)]     = bf2(acc.x, acc.y);
        sX[pos * PR + permw(2 * c4 + 1)] = bf2(acc.z, acc.w);
    }
    __syncthreads();

    int wid = tid >> 5, lane = tid & 31, grp = lane >> 2, qd = lane & 3;
    int half = wid >> 2;
    int r0 = (wid & 3) * 16 + grp;
    float sc[8][4];
    proj_mma(sX, half ? sWv : sWk, sc, r0, grp, qd);

    if (half == 0) {
        store_nmaj(g_kp + (size_t)gpos0 * 32, sc, sb, r0, qd);
    } else {
        #pragma unroll
        for (int nt = 0; nt < 8; nt++) {
            float2 bb = *(const float2*)(sb + 64 + 8 * nt + 2 * qd);
            st[r0 * 67 + 8 * nt + 2 * qd]     = sc[nt][0] + bb.x;
            st[r0 * 67 + 8 * nt + 2 * qd + 1] = sc[nt][1] + bb.y;
            st[(r0 + 8) * 67 + 8 * nt + 2 * qd]     = sc[nt][2] + bb.x;
            st[(r0 + 8) * 67 + 8 * nt + 2 * qd + 1] = sc[nt][3] + bb.y;
        }
    }
    __syncthreads();

    u32* out = g_vp + (size_t)b * 64 * 16 * 32;
    int ktb = j0 >> 6;
    for (int i = tid; i < 2048; i += 256) {
        int w = i & 31, cout = i >> 5;
        float v0 = st[(2 * w) * 67 + cout];
        float v1 = st[(2 * w + 1) * 67 + cout];
        out[((size_t)cout * 16 + ktb) * 32 + permw(w)] = bf2(v0, v1);
    }
}

// ================= pipelined bf16 flash attention ==========================
// CTA = 128 q-rows, 8 warps x 16 q-rows, 64-key tiles.
// K double-buffered, V triple-buffered; prefetch distance 2; S-MMA of tile
// k+1 issued BEFORE softmax(k) so tensor work overlaps the softmax chain;
// exp computation fused into PV k-steps; l-sum shuffles deferred to the end.

__device__ __forceinline__ void attn_S(const u32* sQ, const u32* sKc,
                                       float sc[8][4], int r0, int grp, int qd)
{
    u32 aQ0[8], aQ1[8];
    #pragma unroll
    for (int u = 0; u < 2; u++) {
        uint4 x0 = *(const uint4*)(sQ + r0 * PR + 8 * qd + 4 * u);
        uint4 x1 = *(const uint4*)(sQ + (r0 + 8) * PR + 8 * qd + 4 * u);
        aQ0[4*u] = x0.x; aQ0[4*u+1] = x0.y; aQ0[4*u+2] = x0.z; aQ0[4*u+3] = x0.w;
        aQ1[4*u] = x1.x; aQ1[4*u+1] = x1.y; aQ1[4*u+2] = x1.z; aQ1[4*u+3] = x1.w;
    }
    #pragma unroll
    for (int nt = 0; nt < 8; nt++) {
        sc[nt][0] = 0.f; sc[nt][1] = 0.f; sc[nt][2] = 0.f; sc[nt][3] = 0.f;
        const u32* bp = sKc + (8 * nt + grp) * PR + 8 * qd;
        uint4 B0 = *(const uint4*)bp;
        uint4 B1 = *(const uint4*)(bp + 4);
        mma_bf16(sc[nt], aQ0[0], aQ1[0], aQ0[1], aQ1[1], B0.x, B0.y);
        mma_bf16(sc[nt], aQ0[2], aQ1[2], aQ0[3], aQ1[3], B0.z, B0.w);
        mma_bf16(sc[nt], aQ0[4], aQ1[4], aQ0[5], aQ1[5], B1.x, B1.y);
        mma_bf16(sc[nt], aQ0[6], aQ1[6], aQ0[7], aQ1[7], B1.z, B1.w);
    }
}

#define ATTN_SMEM ((128 + 5*64) * PR * 4)   // 64512 B

template<bool FINAL>
__global__ __launch_bounds__(256, 2)
void attn_kernel(float* __restrict__ outg,
                 const float* __restrict__ xr,
                 const float* __restrict__ gp)
{
    constexpr int NKEY = FINAL ? 1024 : 4096;
    constexpr int NQ   = FINAL ? 4096 : 1024;
    constexpr int NT   = NKEY / 64;

    extern __shared__ u32 sm[];
    u32* sQ = sm;                        // 128*36
    u32* kb[2] = { sm + 128 * PR, sm + 192 * PR };
    u32* vb[3] = { sm + 256 * PR, sm + 320 * PR, sm + 384 * PR };

    int tid = threadIdx.x;
    int wid = tid >> 5, lane = tid & 31;
    int grp = lane >> 2, qd = lane & 3;
    int b = blockIdx.y, qt = blockIdx.x;
    int part = FINAL ? 0 : blockIdx.z;

    const u32* Qg = (FINAL ? g_Q  : g_qp) + ((size_t)b * NQ + qt * 128) * 32;
    const u32* Kg = (FINAL ? g_kp : g_K ) + (size_t)b * NKEY * 32;
    const u32* Vg = (FINAL ? g_vp : g_V ) + (size_t)b * C_ * NT * 32;

    int nkt = FINAL ? NT : NT / SPLIT1;
    int kt0 = part * nkt;

    // Q + tile0 direct loads.
    #pragma unroll
    for (int r = 0; r < 4; r++) {
        int idx = r * 256 + tid;
        int row = idx >> 3, q4 = (idx & 7) * 4;
        *(uint4*)(sQ + row * PR + q4) = *(const uint4*)(Qg + (size_t)row * 32 + q4);
    }
    #pragma unroll
    for (int r = 0; r < 2; r++) {
        int idx = r * 256 + tid;
        int row = idx >> 3, q4 = (idx & 7) * 4;
        *(uint4*)(kb[0] + row * PR + q4) =
            *(const uint4*)(Kg + ((size_t)kt0 * 64 + row) * 32 + q4);
        *(uint4*)(vb[0] + row * PR + q4) =
            *(const uint4*)(Vg + ((size_t)row * NT + kt0) * 32 + q4);
    }
    // Prefetch tile 1.
    if (nkt > 1) {
        int kt = kt0 + 1;
        #pragma unroll
        for (int r = 0; r < 2; r++) {
            int idx = r * 256 + tid;
            int row = idx >> 3, q4 = (idx & 7) * 4;
            cpa16(kb[1] + row * PR + q4, Kg + ((size_t)kt * 64 + row) * 32 + q4);
            cpa16(vb[1] + row * PR + q4, Vg + ((size_t)row * NT + kt) * 32 + q4);
        }
        CP_COMMIT();
    }
    __syncthreads();

    int r0 = wid * 16 + grp;
    float m0 = -1e30f, m1 = -1e30f, ll0 = 0.f, ll1 = 0.f;
    float oc[8][4];
    #pragma unroll
    for (int nt = 0; nt < 8; nt++) {
        oc[nt][0] = 0.f; oc[nt][1] = 0.f; oc[nt][2] = 0.f; oc[nt][3] = 0.f;
    }

    float scc[8][4];
    attn_S(sQ, kb[0], scc, r0, grp, qd);

    for (int kk = 0; kk < nkt; kk++) {
        const u32* sVc = vb[kk % 3];
        bool hasN = (kk + 1 < nkt);

        if (hasN) CP_WAIT0();
        __syncthreads();   // tile kk+1 visible; all warps done with vb[(kk+2)%3]

        // Prefetch tile kk+2 (overlaps this whole iteration).
        if (kk + 2 < nkt) {
            int kt = kt0 + kk + 2;
            u32* kd = kb[kk & 1];
            u32* vd = vb[(kk + 2) % 3];
            #pragma unroll
            for (int r = 0; r < 2; r++) {
                int idx = r * 256 + tid;
                int row = idx >> 3, q4 = (idx & 7) * 4;
                cpa16(kd + row * PR + q4, Kg + ((size_t)kt * 64 + row) * 32 + q4);
                cpa16(vd + row * PR + q4, Vg + ((size_t)row * NT + kt) * 32 + q4);
            }
            CP_COMMIT();
        }

        // S-MMA for NEXT tile issued before this tile's softmax (overlap).
        float scn[8][4];
        if (hasN) attn_S(sQ, kb[(kk + 1) & 1], scn, r0, grp, qd);

        // Softmax head: row max, alpha, rescale.
        float rx0 = -1e30f, rx1 = -1e30f;
        #pragma unroll
        for (int nt = 0; nt < 8; nt++) {
            rx0 = fmaxf(rx0, fmaxf(scc[nt][0], scc[nt][1]));
            rx1 = fmaxf(rx1, fmaxf(scc[nt][2], scc[nt][3]));
        }
        rx0 = fmaxf(rx0, __shfl_xor_sync(0xffffffffu, rx0, 1));
        rx0 = fmaxf(rx0, __shfl_xor_sync(0xffffffffu, rx0, 2));
        rx1 = fmaxf(rx1, __shfl_xor_sync(0xffffffffu, rx1, 1));
        rx1 = fmaxf(rx1, __shfl_xor_sync(0xffffffffu, rx1, 2));
        float mn0 = fmaxf(m0, rx0), mn1 = fmaxf(m1, rx1);
        float al0 = ex2(m0 - mn0), al1 = ex2(m1 - mn1);
        m0 = mn0; m1 = mn1;
        ll0 *= al0; ll1 *= al1;
        #pragma unroll
        for (int nt = 0; nt < 8; nt++) {
            oc[nt][0] *= al0; oc[nt][1] *= al0;
            oc[nt][2] *= al1; oc[nt][3] *= al1;
        }

        // Fused exp + PV: k-step s consumes score-tiles 2s, 2s+1.
        #pragma unroll
        for (int s = 0; s < 4; s++) {
            float pa0 = ex2(scc[2*s][0] - m0),   pa1 = ex2(scc[2*s][1] - m0);
            float pa2 = ex2(scc[2*s][2] - m1),   pa3 = ex2(scc[2*s][3] - m1);
            float pb0 = ex2(scc[2*s+1][0] - m0), pb1 = ex2(scc[2*s+1][1] - m0);
            float pb2 = ex2(scc[2*s+1][2] - m1), pb3 = ex2(scc[2*s+1][3] - m1);
            ll0 += (pa0 + pa1) + (pb0 + pb1);
            ll1 += (pa2 + pa3) + (pb2 + pb3);
            u32 A0 = bf2(pa0, pa1), A1 = bf2(pa2, pa3);
            u32 A2 = bf2(pb0, pb1), A3 = bf2(pb2, pb3);
            #pragma unroll
            for (int nt = 0; nt < 8; nt++) {
                uint2 bb = *(const uint2*)(sVc + (8 * nt + grp) * PR + 8 * qd + 2 * s);
                mma_bf16(oc[nt], A0, A1, A2, A3, bb.x, bb.y);
            }
        }

        if (hasN) {
            #pragma unroll
            for (int nt = 0; nt < 8; nt++) {
                scc[nt][0] = scn[nt][0]; scc[nt][1] = scn[nt][1];
                scc[nt][2] = scn[nt][2]; scc[nt][3] = scn[nt][3];
            }
        }
    }

    // Finalize l (deferred cross-lane reduction).
    ll0 += __shfl_xor_sync(0xffffffffu, ll0, 1);
    ll0 += __shfl_xor_sync(0xffffffffu, ll0, 2);
    ll1 += __shfl_xor_sync(0xffffffffu, ll1, 1);
    ll1 += __shfl_xor_sync(0xffffffffu, ll1, 2);

    if (!FINAL) {
        size_t mlidx = (size_t)(part * B_ + b) * N4_ + qt * 128 + r0;
        #pragma unroll
        for (int nt = 0; nt < 8; nt++) {
            *(float2*)(g_po + mlidx * 64 + 8 * nt + 2 * qd) =
                make_float2(oc[nt][0], oc[nt][1]);
            *(float2*)(g_po + (mlidx + 8) * 64 + 8 * nt + 2 * qd) =
                make_float2(oc[nt][2], oc[nt][3]);
        }
        if (qd == 0) {
            g_m2[mlidx] = m0; g_l2[mlidx] = ll0;
            g_m2[mlidx + 8] = m1; g_l2[mlidx + 8] = ll1;
        }
    } else {
        float* st = (float*)sm;
        float inv0 = 1.f / ll0, inv1 = 1.f / ll1;
        __syncthreads();   // all warps past final PV before overlaying smem
        #pragma unroll
        for (int nt = 0; nt < 8; nt++) {
            *(float2*)(st + r0 * 66 + 8 * nt + 2 * qd) =
                make_float2(oc[nt][0] * inv0, oc[nt][1] * inv0);
            *(float2*)(st + (r0 + 8) * 66 + 8 * nt + 2 * qd) =
                make_float2(oc[nt][2] * inv1, oc[nt][3] * inv1);
        }
        __syncthreads();
        float gamma = gp[0];
        int n0 = qt * 128;
        #pragma unroll 4
        for (int r2 = 0; r2 < 32; r2++) {
            int idx = r2 * 256 + tid;
            int c = idx >> 7, nl = idx & 127;
            size_t ga = ((size_t)b * 64 + c) * (size_t)N_ + n0 + nl;
            outg[ga] = gamma * st[nl * 66 + c] + xr[ga];
        }
    }
}

// ---------------- Launch ----------------

extern "C" void kernel_launch(void* const* d_in, const int* in_sizes, int n_in,
                              void* d_out, int out_size)
{
    (void)in_sizes; (void)n_in; (void)out_size;
    const float* x     = (const float*)d_in[0];
    const float* w_q   = (const float*)d_in[1];
    const float* b_q   = (const float*)d_in[2];
    const float* w_K   = (const float*)d_in[3];
    const float* b_K   = (const float*)d_in[4];
    const float* w_V   = (const float*)d_in[5];
    const float* b_V   = (const float*)d_in[6];
    const float* w_Q   = (const float*)d_in[7];
    const float* b_Q   = (const float*)d_in[8];
    const float* w_k   = (const float*)d_in[9];
    const float* b_k   = (const float*)d_in[10];
    const float* w_v   = (const float*)d_in[11];
    const float* b_v   = (const float*)d_in[12];
    const float* gamma = (const float*)d_in[13];
    float* out = (float*)d_out;

    cudaFuncSetAttribute(projX_kernel, cudaFuncAttributeMaxDynamicSharedMemorySize, PROJX_SMEM);
    cudaFuncSetAttribute(projC_kernel, cudaFuncAttributeMaxDynamicSharedMemorySize, PROJC_SMEM);
    cudaFuncSetAttribute(attn_kernel<false>, cudaFuncAttributeMaxDynamicSharedMemorySize, ATTN_SMEM);
    cudaFuncSetAttribute(attn_kernel<true>,  cudaFuncAttributeMaxDynamicSharedMemorySize, ATTN_SMEM);

    // All stage-1 projections + pooled q in ONE launch (y: 0=K 1=V 2=Q 3=qp).
    projX_kernel<<<dim3(B_*N_/128, 4), 256, PROJX_SMEM>>>(
        x, w_K, b_K, w_V, b_V, w_Q, b_Q, w_q, b_q);

    // Stage 1 attention: split-K over 4 parts (8 x 8 x 4 = 256 CTAs).
    attn_kernel<false><<<dim3(N4_/128, B_, SPLIT1), 256, ATTN_SMEM>>>(nullptr, nullptr, nullptr);

    // Stage 2 projections: single fused combine + kp/vp MMAs (128 CTAs).
    projC_kernel<<<BN4/64, 256, PROJC_SMEM>>>(w_k, b_k, w_v, b_v);

    // Stage 2 attention + residual epilogue (32 x 8 = 256 CTAs).
    attn_kernel<true><<<dim3(N_/128, B_), 256, ATTN_SMEM>>>(out, x, gamma);
}

// round 17
// speedup vs baseline: 1.2939x; 1.2939x over previous
#include <cuda_runtime.h>
#include <cstdint>
#include <cstddef>

#define B_  8
#define C_  64
#define N_  4096
#define N4_ 1024
#define SPLIT1 4
#define BN4 (B_*N4_)
#define PR 36
#define LOG2E 1.4426950408889634f

typedef unsigned long long u64;
typedef unsigned int u32;

// bf16 operands as bf16x2 words; per row 32 words over the 64-elt contraction
// dim, word w stored at perm p(w) = (w&3)*8 + (w>>2).
__device__ u32 g_K [B_*N_*32];          // (b,key)[32]     stage1 keys
__device__ u32 g_V [B_*C_*(N_/64)*32];  // (b,c,ktile)[32] stage1 values
__device__ u32 g_Q [B_*N_*32];          // (b,q)[32]       stage2 queries (pre-scaled by log2e)
__device__ u32 g_qp[B_*N4_*32];         // (b,j)[32]       stage1 pooled queries (pre-scaled)
__device__ u32 g_kp[B_*N4_*32];         // (b,j)[32]       stage2 keys
__device__ u32 g_vp[B_*C_*(N4_/64)*32]; // (b,c,ktile)[32] stage2 values
__device__ float g_po[SPLIT1*BN4*C_];   // split-K partials (unnormalized)
__device__ float g_m2[SPLIT1*BN4];
__device__ float g_l2[SPLIT1*BN4];

__device__ __forceinline__ u32 bf2(float lo, float hi) {
    u32 r; asm("cvt.rn.bf16x2.f32 %0, %1, %2;" : "=r"(r) : "f"(hi), "f"(lo)); return r;
}
__device__ __forceinline__ float ex2(float x) {
    float r; asm("ex2.approx.f32 %0, %1;" : "=f"(r) : "f"(x)); return r;
}
__device__ __forceinline__ int permw(int w) { return (w & 3) * 8 + (w >> 2); }

__device__ __forceinline__ void cpa16(u32* dst, const u32* src) {
    u32 d = (u32)__cvta_generic_to_shared(dst);
    asm volatile("cp.async.ca.shared.global [%0], [%1], 16;" :: "r"(d), "l"(src));
}
#define CP_COMMIT() asm volatile("cp.async.commit_group;" ::: "memory")
#define CP_WAIT0()  asm volatile("cp.async.wait_group 0;" ::: "memory")

__device__ __forceinline__ void mma_bf16(float c[4], u32 a0, u32 a1, u32 a2, u32 a3,
                                         u32 b0, u32 b1) {
    asm volatile(
        "mma.sync.aligned.m16n8k16.row.col.f32.bf16.bf16.f32 "
        "{%0,%1,%2,%3},{%4,%5,%6,%7},{%8,%9},{%0,%1,%2,%3};"
        : "+f"(c[0]), "+f"(c[1]), "+f"(c[2]), "+f"(c[3])
        : "r"(a0), "r"(a1), "r"(a2), "r"(a3), "r"(b0), "r"(b1));
}

// ================= bf16-MMA projection core (unchanged R15) ================

__device__ __forceinline__ void stage_W(const float* __restrict__ w,
                                        const float* __restrict__ bias,
                                        u32* sW, float* sb, int tid, float scale)
{
    for (int i = tid; i < 1024; i += 256) {
        int o = i >> 4, t = i & 15;
        float4 v = *(const float4*)(w + o * 64 + 4 * t);
        sW[o * PR + permw(2 * t)]     = bf2(v.x * scale, v.y * scale);
        sW[o * PR + permw(2 * t + 1)] = bf2(v.z * scale, v.w * scale);
    }
    if (tid < 64) sb[tid] = bias[tid] * scale;
}

__device__ __forceinline__ void proj_mma(const u32* sX, const u32* sW,
                                         float sc[8][4], int r0, int grp, int qd)
{
    u32 a0[8], a1[8];
    #pragma unroll
    for (int u = 0; u < 2; u++) {
        uint4 x0 = *(const uint4*)(sX + r0 * PR + 8 * qd + 4 * u);
        uint4 x1 = *(const uint4*)(sX + (r0 + 8) * PR + 8 * qd + 4 * u);
        a0[4*u] = x0.x; a0[4*u+1] = x0.y; a0[4*u+2] = x0.z; a0[4*u+3] = x0.w;
        a1[4*u] = x1.x; a1[4*u+1] = x1.y; a1[4*u+2] = x1.z; a1[4*u+3] = x1.w;
    }
    #pragma unroll
    for (int nt = 0; nt < 8; nt++) {
        sc[nt][0] = 0.f; sc[nt][1] = 0.f; sc[nt][2] = 0.f; sc[nt][3] = 0.f;
        const u32* bp = sW + (8 * nt + grp) * PR + 8 * qd;
        uint4 B0 = *(const uint4*)bp;
        uint4 B1 = *(const uint4*)(bp + 4);
        mma_bf16(sc[nt], a0[0], a1[0], a0[1], a1[1], B0.x, B0.y);
        mma_bf16(sc[nt], a0[2], a1[2], a0[3], a1[3], B0.z, B0.w);
        mma_bf16(sc[nt], a0[4], a1[4], a0[5], a1[5], B1.x, B1.y);
        mma_bf16(sc[nt], a0[6], a1[6], a0[7], a1[7], B1.z, B1.w);
    }
}

__device__ __forceinline__ void store_nmaj(u32* __restrict__ dst,
                                           const float sc[8][4], const float* sb,
                                           int r0, int qd)
{
    u32 w0[8], w1[8];
    #pragma unroll
    for (int nt = 0; nt < 8; nt++) {
        float2 bb = *(const float2*)(sb + 8 * nt + 2 * qd);
        w0[nt] = bf2(sc[nt][0] + bb.x, sc[nt][1] + bb.y);
        w1[nt] = bf2(sc[nt][2] + bb.x, sc[nt][3] + bb.y);
    }
    *(uint4*)(dst + (size_t)r0 * 32 + 8 * qd)     = make_uint4(w0[0], w0[1], w0[2], w0[3]);
    *(uint4*)(dst + (size_t)r0 * 32 + 8 * qd + 4) = make_uint4(w0[4], w0[5], w0[6], w0[7]);
    *(uint4*)(dst + (size_t)(r0 + 8) * 32 + 8 * qd)     = make_uint4(w1[0], w1[1], w1[2], w1[3]);
    *(uint4*)(dst + (size_t)(r0 + 8) * 32 + 8 * qd + 4) = make_uint4(w1[4], w1[5], w1[6], w1[7]);
}

__device__ __forceinline__ void store_cmaj128(u32* __restrict__ out, int NT, int ktbase,
                                              float* st, const float sc[8][4],
                                              const float* sb, int r0, int qd, int tid)
{
    __syncthreads();
    #pragma unroll
    for (int nt = 0; nt < 8; nt++) {
        float2 bb = *(const float2*)(sb + 8 * nt + 2 * qd);
        st[r0 * 67 + 8 * nt + 2 * qd]     = sc[nt][0] + bb.x;
        st[r0 * 67 + 8 * nt + 2 * qd + 1] = sc[nt][1] + bb.y;
        st[(r0 + 8) * 67 + 8 * nt + 2 * qd]     = sc[nt][2] + bb.x;
        st[(r0 + 8) * 67 + 8 * nt + 2 * qd + 1] = sc[nt][3] + bb.y;
    }
    __syncthreads();
    for (int i = tid; i < 4096; i += 256) {
        int w = i & 31, tile = (i >> 5) & 1, cout = i >> 6;
        float v0 = st[(tile * 64 + 2 * w) * 67 + cout];
        float v1 = st[(tile * 64 + 2 * w + 1) * 67 + cout];
        out[((size_t)cout * NT + ktbase + tile) * 32 + permw(w)] = bf2(v0, v1);
    }
}

#define PROJX_SMEM ((128*67 + 64) * 4)
__global__ __launch_bounds__(256)
void projX_kernel(const float* __restrict__ x,
                  const float* __restrict__ wK, const float* __restrict__ bK,
                  const float* __restrict__ wV, const float* __restrict__ bV,
                  const float* __restrict__ wQ, const float* __restrict__ bQ,
                  const float* __restrict__ wq, const float* __restrict__ bq)
{
    int which = blockIdx.y;
    if (which == 3 && blockIdx.x >= B_*N4_/128) return;

    extern __shared__ u32 sm[];
    u32* sX = sm;
    u32* sW = sm + 128 * PR;
    float* st = (float*)sm;
    float* sb = (float*)(sm + 128 * 67);
    int tid = threadIdx.x;
    const float* w  = which == 0 ? wK : (which == 1 ? wV : (which == 2 ? wQ : wq));
    const float* bs = which == 0 ? bK : (which == 1 ? bV : (which == 2 ? bQ : bq));
    stage_W(w, bs, sW, sb, tid, which >= 2 ? LOG2E : 1.0f);

    if (which != 3) {
        int gpos0 = blockIdx.x * 128;
        int b = gpos0 >> 12, n0 = gpos0 & (N_ - 1);
        const float* xb = x + (size_t)b * C_ * N_ + n0;
        #pragma unroll
        for (int it = 0; it < 2; it++) {
            int idx = it * 256 + tid;
            int pos = idx & 127, a = idx >> 7;
            u32 wb[8];
            #pragma unroll
            for (int j = 0; j < 8; j++) {
                int ch = 8 * j + 2 * a;
                wb[j] = bf2(xb[(size_t)ch * N_ + pos], xb[(size_t)(ch + 1) * N_ + pos]);
            }
            *(uint4*)(sX + pos * PR + 8 * a)     = make_uint4(wb[0], wb[1], wb[2], wb[3]);
            *(uint4*)(sX + pos * PR + 8 * a + 4) = make_uint4(wb[4], wb[5], wb[6], wb[7]);
        }
        __syncthreads();

        int wid = tid >> 5, lane = tid & 31, grp = lane >> 2, qd = lane & 3;
        int r0 = wid * 16 + grp;
        float sc[8][4];
        proj_mma(sX, sW, sc, r0, grp, qd);
        if (which == 0)      store_nmaj(g_K + (size_t)gpos0 * 32, sc, sb, r0, qd);
        else if (which == 2) store_nmaj(g_Q + (size_t)gpos0 * 32, sc, sb, r0, qd);
        else store_cmaj128(g_V + (size_t)b * 64 * 64 * 32, 64, n0 >> 6, st, sc, sb, r0, qd, tid);
    } else {
        int gpos0 = blockIdx.x * 128;
        int b = gpos0 >> 10, j0 = gpos0 & (N4_ - 1);
        const float* xb = x + (size_t)b * C_ * N_;
        #pragma unroll
        for (int it = 0; it < 2; it++) {
            int idx = it * 256 + tid;
            int pos = idx & 127, a = idx >> 7;
            int jj = j0 + pos;
            size_t base = (size_t)(jj >> 5) * 128 + (jj & 31) * 2;
            u32 wb[8];
            #pragma unroll
            for (int j = 0; j < 8; j++) {
                int ch = 8 * j + 2 * a;
                const float* p0 = xb + (size_t)ch * N_ + base;
                const float* p1 = xb + (size_t)(ch + 1) * N_ + base;
                float v0 = 0.25f * (p0[0] + p0[1] + p0[64] + p0[65]);
                float v1 = 0.25f * (p1[0] + p1[1] + p1[64] + p1[65]);
                wb[j] = bf2(v0, v1);
            }
            *(uint4*)(sX + pos * PR + 8 * a)     = make_uint4(wb[0], wb[1], wb[2], wb[3]);
            *(uint4*)(sX + pos * PR + 8 * a + 4) = make_uint4(wb[4], wb[5], wb[6], wb[7]);
        }
        __syncthreads();

        int wid = tid >> 5, lane = tid & 31, grp = lane >> 2, qd = lane & 3;
        int r0 = wid * 16 + grp;
        float sc[8][4];
        proj_mma(sX, sW, sc, r0, grp, qd);
        store_nmaj(g_qp + (size_t)gpos0 * 32, sc, sb, r0, qd);
    }
}

#define PC_SX   0
#define PC_SWK  (64*PR)
#define PC_SWV  (PC_SWK + 64*PR)
#define PC_ST   (PC_SWV + 64*PR)
#define PC_SB   (PC_ST + 64*67)
#define PC_SWT  (PC_SB + 128)
#define PROJC_SMEM ((PC_SWT + 256) * 4)
__global__ __launch_bounds__(256)
void projC_kernel(const float* __restrict__ wk, const float* __restrict__ bk,
                  const float* __restrict__ wv, const float* __restrict__ bv)
{
    extern __shared__ u32 sm[];
    u32* sX  = sm + PC_SX;
    u32* sWk = sm + PC_SWK;
    u32* sWv = sm + PC_SWV;
    float* st  = (float*)(sm + PC_ST);
    float* sb  = (float*)(sm + PC_SB);
    float* swt = (float*)(sm + PC_SWT);
    int tid = threadIdx.x;
    stage_W(wk, bk, sWk, sb, tid, 1.0f);
    stage_W(wv, bv, sWv, sb + 64, tid, 1.0f);

    int gpos0 = blockIdx.x * 64;
    int b = gpos0 >> 10, j0 = gpos0 & (N4_ - 1);

    if (tid < 64) {
        int grow = gpos0 + tid;
        float mv[SPLIT1], lv[SPLIT1], M = -1e30f;
        #pragma unroll
        for (int p = 0; p < SPLIT1; p++) {
            mv[p] = g_m2[p * BN4 + grow];
            lv[p] = g_l2[p * BN4 + grow];
            M = fmaxf(M, mv[p]);
        }
        float wv_[SPLIT1], ls = 0.f;
        #pragma unroll
        for (int p = 0; p < SPLIT1; p++) { wv_[p] = ex2(mv[p] - M); ls += lv[p] * wv_[p]; }
        float inv = 1.f / ls;
        #pragma unroll
        for (int p = 0; p < SPLIT1; p++) swt[tid * 4 + p] = wv_[p] * inv;
    }
    __syncthreads();

    for (int i = tid; i < 1024; i += 256) {
        int c4 = i & 15, pos = i >> 4;
        const float* wp = swt + pos * 4;
        float4 acc = make_float4(0.f, 0.f, 0.f, 0.f);
        #pragma unroll
        for (int p = 0; p < SPLIT1; p++) {
            float4 a = *(const float4*)(g_po + ((size_t)p * BN4 + gpos0 + pos) * 64 + 4 * c4);
            float wf = wp[p];
            acc.x += wf * a.x; acc.y += wf * a.y; acc.z += wf * a.z; acc.w += wf * a.w;
        }
        sX[pos * PR + permw(2 * c4)]     = bf2(acc.x, acc.y);
        sX[pos * PR + permw(2 * c4 + 1)] = bf2(acc.z, acc.w);
    }
    __syncthreads();

    int wid = tid >> 5, lane = tid & 31, grp = lane >> 2, qd = lane & 3;
    int half = wid >> 2;
    int r0 = (wid & 3) * 16 + grp;
    float sc[8][4];
    proj_mma(sX, half ? sWv : sWk, sc, r0, grp, qd);

    if (half == 0) {
        store_nmaj(g_kp + (size_t)gpos0 * 32, sc, sb, r0, qd);
    } else {
        #pragma unroll
        for (int nt = 0; nt < 8; nt++) {
            float2 bb = *(const float2*)(sb + 64 + 8 * nt + 2 * qd);
            st[r0 * 67 + 8 * nt + 2 * qd]     = sc[nt][0] + bb.x;
            st[r0 * 67 + 8 * nt + 2 * qd + 1] = sc[nt][1] + bb.y;
            st[(r0 + 8) * 67 + 8 * nt + 2 * qd]     = sc[nt][2] + bb.x;
            st[(r0 + 8) * 67 + 8 * nt + 2 * qd + 1] = sc[nt][3] + bb.y;
        }
    }
    __syncthreads();

    u32* out = g_vp + (size_t)b * 64 * 16 * 32;
    int ktb = j0 >> 6;
    for (int i = tid; i < 2048; i += 256) {
        int w = i & 31, cout = i >> 5;
        float v0 = st[(2 * w) * 67 + cout];
        float v1 = st[(2 * w + 1) * 67 + cout];
        out[((size_t)cout * 16 + ktb) * 32 + permw(w)] = bf2(v0, v1);
    }
}

// ================= bf16 m16n8k16 flash attention (R15 core + fused PV) =====
// CTA = 128 q-rows, 8 warps x 16 q-rows, 64-key tiles, cp.async double buffer.
// Per tile: S-MMA -> softmax head -> FUSED exp+PV (exp of score-tiles 2s,2s+1
// feeds PV k-step s directly; no prow arrays) -> barrier. l-sum reduced once
// at the end (per-lane partials are exact: same alpha sequence every lane).

template<bool FINAL>
__global__ __launch_bounds__(256, 2)
void attn_kernel(float* __restrict__ outg,
                 const float* __restrict__ xr,
                 const float* __restrict__ gp)
{
    constexpr int NKEY = FINAL ? 1024 : 4096;
    constexpr int NQ   = FINAL ? 4096 : 1024;
    constexpr int NT   = NKEY / 64;

    extern __shared__ u32 sm[];
    u32* sQ  = sm;                 // 128*36
    u32* sK0 = sQ  + 128 * PR;     // 64*36
    u32* sV0 = sK0 + 64 * PR;
    u32* sK1 = sV0 + 64 * PR;
    u32* sV1 = sK1 + 64 * PR;      // total 384*36 words

    int tid = threadIdx.x;
    int wid = tid >> 5, lane = tid & 31;
    int grp = lane >> 2, qd = lane & 3;
    int b = blockIdx.y, qt = blockIdx.x;
    int part = FINAL ? 0 : blockIdx.z;

    const u32* Qg = (FINAL ? g_Q  : g_qp) + ((size_t)b * NQ + qt * 128) * 32;
    const u32* Kg = (FINAL ? g_kp : g_K ) + (size_t)b * NKEY * 32;
    const u32* Vg = (FINAL ? g_vp : g_V ) + (size_t)b * C_ * NT * 32;

    int nkt = FINAL ? NT : NT / SPLIT1;
    int kt0 = part * nkt;

    #pragma unroll
    for (int r = 0; r < 4; r++) {
        int idx = r * 256 + tid;
        int row = idx >> 3, q4 = (idx & 7) * 4;
        *(uint4*)(sQ + row * PR + q4) = *(const uint4*)(Qg + (size_t)row * 32 + q4);
    }
    #pragma unroll
    for (int r = 0; r < 2; r++) {
        int idx = r * 256 + tid;
        int row = idx >> 3, q4 = (idx & 7) * 4;
        *(uint4*)(sK0 + row * PR + q4) =
            *(const uint4*)(Kg + ((size_t)kt0 * 64 + row) * 32 + q4);
        *(uint4*)(sV0 + row * PR + q4) =
            *(const uint4*)(Vg + ((size_t)row * NT + kt0) * 32 + q4);
    }
    __syncthreads();

    int r0 = wid * 16 + grp;
    u32 aQ0[8], aQ1[8];
    #pragma unroll
    for (int u = 0; u < 2; u++) {
        uint4 x0 = *(const uint4*)(sQ + r0 * PR + 8 * qd + 4 * u);
        uint4 x1 = *(const uint4*)(sQ + (r0 + 8) * PR + 8 * qd + 4 * u);
        aQ0[4*u] = x0.x; aQ0[4*u+1] = x0.y; aQ0[4*u+2] = x0.z; aQ0[4*u+3] = x0.w;
        aQ1[4*u] = x1.x; aQ1[4*u+1] = x1.y; aQ1[4*u+2] = x1.z; aQ1[4*u+3] = x1.w;
    }

    float m0 = -1e30f, m1 = -1e30f, ll0 = 0.f, ll1 = 0.f;
    float oc[8][4];
    #pragma unroll
    for (int nt = 0; nt < 8; nt++) {
        oc[nt][0] = 0.f; oc[nt][1] = 0.f; oc[nt][2] = 0.f; oc[nt][3] = 0.f;
    }

    for (int kk = 0; kk < nkt; kk++) {
        const u32* sKc = (kk & 1) ? sK1 : sK0;
        const u32* sVc = (kk & 1) ? sV1 : sV0;
        u32* sKn = (kk & 1) ? sK0 : sK1;
        u32* sVn = (kk & 1) ? sV0 : sV1;

        bool hasNext = (kk + 1 < nkt);
        if (hasNext) {
            int kt = kt0 + kk + 1;
            #pragma unroll
            for (int r = 0; r < 2; r++) {
                int idx = r * 256 + tid;
                int row = idx >> 3, q4 = (idx & 7) * 4;
                cpa16(sKn + row * PR + q4, Kg + ((size_t)kt * 64 + row) * 32 + q4);
                cpa16(sVn + row * PR + q4, Vg + ((size_t)row * NT + kt) * 32 + q4);
            }
            CP_COMMIT();
        }

        // S = Q K^T (log2 domain).
        float sc[8][4];
        #pragma unroll
        for (int nt = 0; nt < 8; nt++) {
            sc[nt][0] = 0.f; sc[nt][1] = 0.f; sc[nt][2] = 0.f; sc[nt][3] = 0.f;
            const u32* bp = sKc + (8 * nt + grp) * PR + 8 * qd;
            uint4 B0 = *(const uint4*)bp;
            uint4 B1 = *(const uint4*)(bp + 4);
            mma_bf16(sc[nt], aQ0[0], aQ1[0], aQ0[1], aQ1[1], B0.x, B0.y);
            mma_bf16(sc[nt], aQ0[2], aQ1[2], aQ0[3], aQ1[3], B0.z, B0.w);
            mma_bf16(sc[nt], aQ0[4], aQ1[4], aQ0[5], aQ1[5], B1.x, B1.y);
            mma_bf16(sc[nt], aQ0[6], aQ1[6], aQ0[7], aQ1[7], B1.z, B1.w);
        }

        // Softmax head: row max, alpha, rescale.
        float rx0 = -1e30f, rx1 = -1e30f;
        #pragma unroll
        for (int nt = 0; nt < 8; nt++) {
            rx0 = fmaxf(rx0, fmaxf(sc[nt][0], sc[nt][1]));
            rx1 = fmaxf(rx1, fmaxf(sc[nt][2], sc[nt][3]));
        }
        rx0 = fmaxf(rx0, __shfl_xor_sync(0xffffffffu, rx0, 1));
        rx0 = fmaxf(rx0, __shfl_xor_sync(0xffffffffu, rx0, 2));
        rx1 = fmaxf(rx1, __shfl_xor_sync(0xffffffffu, rx1, 1));
        rx1 = fmaxf(rx1, __shfl_xor_sync(0xffffffffu, rx1, 2));
        float mn0 = fmaxf(m0, rx0), mn1 = fmaxf(m1, rx1);
        float al0 = ex2(m0 - mn0), al1 = ex2(m1 - mn1);
        m0 = mn0; m1 = mn1;
        ll0 *= al0; ll1 *= al1;
        #pragma unroll
        for (int nt = 0; nt < 8; nt++) {
            oc[nt][0] *= al0; oc[nt][1] *= al0;
            oc[nt][2] *= al1; oc[nt][3] *= al1;
        }

        // Fused exp + PV: k-step s consumes score-tiles 2s, 2s+1 directly.
        #pragma unroll
        for (int s = 0; s < 4; s++) {
            float pa0 = ex2(sc[2*s][0] - m0),   pa1 = ex2(sc[2*s][1] - m0);
            float pa2 = ex2(sc[2*s][2] - m1),   pa3 = ex2(sc[2*s][3] - m1);
            float pb0 = ex2(sc[2*s+1][0] - m0), pb1 = ex2(sc[2*s+1][1] - m0);
            float pb2 = ex2(sc[2*s+1][2] - m1), pb3 = ex2(sc[2*s+1][3] - m1);
            ll0 += (pa0 + pa1) + (pb0 + pb1);
            ll1 += (pa2 + pa3) + (pb2 + pb3);
            u32 A0 = bf2(pa0, pa1), A1 = bf2(pa2, pa3);
            u32 A2 = bf2(pb0, pb1), A3 = bf2(pb2, pb3);
            #pragma unroll
            for (int nt = 0; nt < 8; nt++) {
                uint2 bb = *(const uint2*)(sVc + (8 * nt + grp) * PR + 8 * qd + 2 * s);
                mma_bf16(oc[nt], A0, A1, A2, A3, bb.x, bb.y);
            }
        }

        if (hasNext) CP_WAIT0();
        __syncthreads();
    }

    // Finalize l (deferred cross-lane reduction; exact, same alphas per lane).
    ll0 += __shfl_xor_sync(0xffffffffu, ll0, 1);
    ll0 += __shfl_xor_sync(0xffffffffu, ll0, 2);
    ll1 += __shfl_xor_sync(0xffffffffu, ll1, 1);
    ll1 += __shfl_xor_sync(0xffffffffu, ll1, 2);

    if (!FINAL) {
        size_t mlidx = (size_t)(part * B_ + b) * N4_ + qt * 128 + r0;
        #pragma unroll
        for (int nt = 0; nt < 8; nt++) {
            *(float2*)(g_po + mlidx * 64 + 8 * nt + 2 * qd) =
                make_float2(oc[nt][0], oc[nt][1]);
            *(float2*)(g_po + (mlidx + 8) * 64 + 8 * nt + 2 * qd) =
                make_float2(oc[nt][2], oc[nt][3]);
        }
        if (qd == 0) {
            g_m2[mlidx] = m0; g_l2[mlidx] = ll0;
            g_m2[mlidx + 8] = m1; g_l2[mlidx + 8] = ll1;
        }
    } else {
        float* st = (float*)sm;
        float inv0 = 1.f / ll0, inv1 = 1.f / ll1;
        #pragma unroll
        for (int nt = 0; nt < 8; nt++) {
            *(float2*)(st + r0 * 66 + 8 * nt + 2 * qd) =
                make_float2(oc[nt][0] * inv0, oc[nt][1] * inv0);
            *(float2*)(st + (r0 + 8) * 66 + 8 * nt + 2 * qd) =
                make_float2(oc[nt][2] * inv1, oc[nt][3] * inv1);
        }
        __syncthreads();
        float gamma = gp[0];
        int n0 = qt * 128;
        #pragma unroll 4
        for (int r2 = 0; r2 < 32; r2++) {
            int idx = r2 * 256 + tid;
            int c = idx >> 7, nl = idx & 127;
            size_t ga = ((size_t)b * 64 + c) * (size_t)N_ + n0 + nl;
            outg[ga] = gamma * st[nl * 66 + c] + xr[ga];
        }
    }
}

// ---------------- Launch ----------------

extern "C" void kernel_launch(void* const* d_in, const int* in_sizes, int n_in,
                              void* d_out, int out_size)
{
    (void)in_sizes; (void)n_in; (void)out_size;
    const float* x     = (const float*)d_in[0];
    const float* w_q   = (const float*)d_in[1];
    const float* b_q   = (const float*)d_in[2];
    const float* w_K   = (const float*)d_in[3];
    const float* b_K   = (const float*)d_in[4];
    const float* w_V   = (const float*)d_in[5];
    const float* b_V   = (const float*)d_in[6];
    const float* w_Q   = (const float*)d_in[7];
    const float* b_Q   = (const float*)d_in[8];
    const float* w_k   = (const float*)d_in[9];
    const float* b_k   = (const float*)d_in[10];
    const float* w_v   = (const float*)d_in[11];
    const float* b_v   = (const float*)d_in[12];
    const float* gamma = (const float*)d_in[13];
    float* out = (float*)d_out;

    const int attn_smem = 384 * PR * 4;   // 55296 B

    cudaFuncSetAttribute(projX_kernel, cudaFuncAttributeMaxDynamicSharedMemorySize, PROJX_SMEM);
    cudaFuncSetAttribute(projC_kernel, cudaFuncAttributeMaxDynamicSharedMemorySize, PROJC_SMEM);
    cudaFuncSetAttribute(attn_kernel<false>, cudaFuncAttributeMaxDynamicSharedMemorySize, attn_smem);
    cudaFuncSetAttribute(attn_kernel<true>,  cudaFuncAttributeMaxDynamicSharedMemorySize, attn_smem);

    // All stage-1 projections + pooled q in ONE launch (y: 0=K 1=V 2=Q 3=qp).
    projX_kernel<<<dim3(B_*N_/128, 4), 256, PROJX_SMEM>>>(
        x, w_K, b_K, w_V, b_V, w_Q, b_Q, w_q, b_q);

    // Stage 1 attention: split-K over 4 parts (8 x 8 x 4 = 256 CTAs).
    attn_kernel<false><<<dim3(N4_/128, B_, SPLIT1), 256, attn_smem>>>(nullptr, nullptr, nullptr);

    // Stage 2 projections: single fused combine + kp/vp MMAs (128 CTAs).
    projC_kernel<<<BN4/64, 256, PROJC_SMEM>>>(w_k, b_k, w_v, b_v);

    // Stage 2 attention + residual epilogue (32 x 8 = 256 CTAs).
    attn_kernel<true><<<dim3(N_/128, B_), 256, attn_smem>>>(out, x, gamma);
}